// round 2
// baseline (speedup 1.0000x reference)
#include <cuda_runtime.h>
#include <math_constants.h>
#include <cstdint>

// Problem constants
#define Bz  4
#define Tz  2048
#define Dz  2048
#define Hz  16
#define HDz 128
#define BHz (Bz*Hz)          // 64
#define Mz  (Bz*Tz)          // 8192

// Scratch (device globals: allocation-free per harness rules)
// q,k stored d-major: [bh][d][t]  (transposed so attention tile loads are clean)
// v stored t-major:   [bh][t][d]
// o stored [b][t][h*HD+d]  (ready for out-proj NT GEMM)
__device__ float g_qT[(size_t)BHz * HDz * Tz];
__device__ float g_kT[(size_t)BHz * HDz * Tz];
__device__ float g_v [(size_t)BHz * Tz * HDz];
__device__ float g_o [(size_t)Mz * Dz];

// ---------------------------------------------------------------------------
// Tiled SGEMM, C = A * B^T.  A:[M,K] rm, B:[N,K] rm.
// 128x128x16 tile, 256 threads, 8x8 microtile.
// MODE 0: A = x, B = w_qkv; epilogue scatters into g_qT/g_kT/g_v.
// MODE 1: A = g_o, B = w_out; epilogue writes C (d_out).
// ---------------------------------------------------------------------------
template<int MODE>
__global__ __launch_bounds__(256, 2)
void sgemm_nt(const float* __restrict__ A, const float* __restrict__ Bm,
              float* __restrict__ C, int M, int N, int K)
{
    __shared__ float As[16][132];
    __shared__ float Bs[16][132];

    const int tid = threadIdx.x;
    const int tx  = tid & 15;
    const int ty  = tid >> 4;
    const int m0  = blockIdx.y * 128;
    const int n0  = blockIdx.x * 128;

    const int lr = tid >> 2;          // 0..63
    const int lk = (tid & 3) << 2;    // 0,4,8,12

    const float* Aact = (MODE == 1) ? (const float*)g_o : A;
    const float* Aptr = Aact + (size_t)(m0 + lr) * K + lk;
    const float* Bptr = Bm   + (size_t)(n0 + lr) * K + lk;

    float acc[8][8];
#pragma unroll
    for (int i = 0; i < 8; i++)
#pragma unroll
        for (int j = 0; j < 8; j++) acc[i][j] = 0.f;

    for (int k0 = 0; k0 < K; k0 += 16) {
        float4 a0 = *(const float4*)(Aptr + k0);
        float4 a1 = *(const float4*)(Aptr + (size_t)64 * K + k0);
        float4 b0 = *(const float4*)(Bptr + k0);
        float4 b1 = *(const float4*)(Bptr + (size_t)64 * K + k0);

        __syncthreads();   // previous compute done reading shared
        As[lk+0][lr]    = a0.x; As[lk+1][lr]    = a0.y; As[lk+2][lr]    = a0.z; As[lk+3][lr]    = a0.w;
        As[lk+0][lr+64] = a1.x; As[lk+1][lr+64] = a1.y; As[lk+2][lr+64] = a1.z; As[lk+3][lr+64] = a1.w;
        Bs[lk+0][lr]    = b0.x; Bs[lk+1][lr]    = b0.y; Bs[lk+2][lr]    = b0.z; Bs[lk+3][lr]    = b0.w;
        Bs[lk+0][lr+64] = b1.x; Bs[lk+1][lr+64] = b1.y; Bs[lk+2][lr+64] = b1.z; Bs[lk+3][lr+64] = b1.w;
        __syncthreads();

#pragma unroll
        for (int kk = 0; kk < 16; kk++) {
            float4 av0 = *(const float4*)&As[kk][ty*4];
            float4 av1 = *(const float4*)&As[kk][ty*4 + 64];
            float4 bv0 = *(const float4*)&Bs[kk][tx*4];
            float4 bv1 = *(const float4*)&Bs[kk][tx*4 + 64];
            float a[8] = {av0.x, av0.y, av0.z, av0.w, av1.x, av1.y, av1.z, av1.w};
            float b[8] = {bv0.x, bv0.y, bv0.z, bv0.w, bv1.x, bv1.y, bv1.z, bv1.w};
#pragma unroll
            for (int i = 0; i < 8; i++)
#pragma unroll
                for (int j = 0; j < 8; j++)
                    acc[i][j] += a[i] * b[j];
        }
    }

    if (MODE == 1) {
#pragma unroll
        for (int i = 0; i < 8; i++) {
            int m = m0 + ((i < 4) ? (ty*4 + i) : (64 + ty*4 + i - 4));
            float4 c0 = make_float4(acc[i][0], acc[i][1], acc[i][2], acc[i][3]);
            float4 c1 = make_float4(acc[i][4], acc[i][5], acc[i][6], acc[i][7]);
            *(float4*)(C + (size_t)m * N + n0 + tx*4)      = c0;
            *(float4*)(C + (size_t)m * N + n0 + tx*4 + 64) = c1;
        }
    } else {
        // N tile (128 wide, aligned) lies entirely inside one of q/k/v + one head
        const int mode = n0 >> 11;            // 0:q 1:k 2:v
        const int h    = (n0 & 2047) >> 7;
        const int b    = m0 >> 11;
        const int t0   = m0 & 2047;
        const int bh   = b * Hz + h;
        if (mode == 2) {
            float* dst = g_v + (size_t)bh * Tz * HDz;
#pragma unroll
            for (int i = 0; i < 8; i++) {
                int t = t0 + ((i < 4) ? (ty*4 + i) : (64 + ty*4 + i - 4));
                float4 c0 = make_float4(acc[i][0], acc[i][1], acc[i][2], acc[i][3]);
                float4 c1 = make_float4(acc[i][4], acc[i][5], acc[i][6], acc[i][7]);
                *(float4*)(dst + (size_t)t * HDz + tx*4)      = c0;
                *(float4*)(dst + (size_t)t * HDz + tx*4 + 64) = c1;
            }
        } else {
            float* dst = (mode == 0) ? g_qT : g_kT;
            const size_t hb = (size_t)bh * HDz;
#pragma unroll
            for (int c = 0; c < 8; c++) {
                int d = (c < 4) ? (tx*4 + c) : (64 + tx*4 + c - 4);
                float4 v0 = make_float4(acc[0][c], acc[1][c], acc[2][c], acc[3][c]);
                float4 v1 = make_float4(acc[4][c], acc[5][c], acc[6][c], acc[7][c]);
                *(float4*)(dst + (hb + d) * Tz + t0 + ty*4)      = v0;
                *(float4*)(dst + (hb + d) * Tz + t0 + 64 + ty*4) = v1;
            }
        }
    }
}

// ---------------------------------------------------------------------------
// RoPE in place on g_qT / g_kT (d-major layout; pairs (d, d+64) at fixed t).
// cos/sin tables satisfy cos[t][d] == cos[t][d+64].
// ---------------------------------------------------------------------------
__global__ void rope_kernel(const float* __restrict__ cosT,
                            const float* __restrict__ sinT)
{
    unsigned idx = blockIdx.x * blockDim.x + threadIdx.x;   // < BH*64*T = 8388608
    int t        = idx & (Tz - 1);
    unsigned r   = idx >> 11;
    int d        = r & 63;
    int bh       = r >> 6;
    size_t base  = ((size_t)bh * HDz + d) * Tz + t;

    float c = cosT[t * HDz + d];
    float s = sinT[t * HDz + d];

    float q1 = g_qT[base], q2 = g_qT[base + (size_t)64 * Tz];
    g_qT[base]                  = q1 * c - q2 * s;
    g_qT[base + (size_t)64*Tz]  = q2 * c + q1 * s;

    float k1 = g_kT[base], k2 = g_kT[base + (size_t)64 * Tz];
    g_kT[base]                  = k1 * c - k2 * s;
    g_kT[base + (size_t)64*Tz]  = k2 * c + k1 * s;
}

// ---------------------------------------------------------------------------
// Causal flash attention, fp32.  BM=BN=64, HD=128, 256 threads (16x16).
// grid = (T/64, B*H).  Shared (dynamic): Qs[128][68], Ks[128][68],
// Vs[64][128], Ps[64][68] = 119808 B.
// ---------------------------------------------------------------------------
#define ATTN_SMEM ((128*68 + 128*68 + 64*128 + 64*68) * 4)

__global__ __launch_bounds__(256, 1)
void attn_kernel()
{
    extern __shared__ float sm[];
    float* Qs = sm;                    // [128][68] (d-major, i contiguous)
    float* Ks = Qs + 128 * 68;         // [128][68]
    float* Vs = Ks + 128 * 68;         // [64][128] (j-major, d contiguous)
    float* Ps = Vs + 64 * 128;         // [64][68]

    const int tid = threadIdx.x;
    const int tx  = tid & 15;
    const int ty  = tid >> 4;
    const int bh  = blockIdx.y;
    const int q0  = blockIdx.x * 64;
    const float scale = 0.08838834764831845f;  // 128^-0.5

    // Load Q tile (pre-scaled)
    const float* qg = g_qT + (size_t)bh * HDz * Tz + q0;
#pragma unroll
    for (int it = 0; it < 8; it++) {
        int idx = tid + it * 256;          // 2048 float4
        int d   = idx >> 4;
        int i4  = (idx & 15) << 2;
        float4 v = *(const float4*)(qg + (size_t)d * Tz + i4);
        v.x *= scale; v.y *= scale; v.z *= scale; v.w *= scale;
        *(float4*)&Qs[d * 68 + i4] = v;
    }

    float m_i[4], l_i[4], oa[4][8];
#pragma unroll
    for (int r = 0; r < 4; r++) {
        m_i[r] = -CUDART_INF_F;
        l_i[r] = 0.f;
#pragma unroll
        for (int c = 0; c < 8; c++) oa[r][c] = 0.f;
    }

    const float* kg = g_kT + (size_t)bh * HDz * Tz;
    const float* vg = g_v  + (size_t)bh * Tz * HDz;
    const int ntiles = blockIdx.x + 1;

    for (int kt = 0; kt < ntiles; kt++) {
        const int j0 = kt * 64;
        __syncthreads();   // prior iteration done reading Ks/Vs/Ps (also fences Q stores, iter 0)
#pragma unroll
        for (int it = 0; it < 8; it++) {
            int idx = tid + it * 256;
            int d   = idx >> 4;
            int i4  = (idx & 15) << 2;
            *(float4*)&Ks[d * 68 + i4] =
                *(const float4*)(kg + (size_t)d * Tz + j0 + i4);
        }
#pragma unroll
        for (int it = 0; it < 8; it++) {
            int idx = tid + it * 256;
            int j   = idx >> 5;
            int ds  = (idx & 31) << 2;
            *(float4*)&Vs[j * 128 + ds] =
                *(const float4*)(vg + (size_t)(j0 + j) * HDz + ds);
        }
        __syncthreads();

        // S = Q K^T (4x4 microtile per thread)
        float s[4][4] = {{0.f,0.f,0.f,0.f},{0.f,0.f,0.f,0.f},
                         {0.f,0.f,0.f,0.f},{0.f,0.f,0.f,0.f}};
#pragma unroll 8
        for (int d = 0; d < 128; d++) {
            float4 qa = *(const float4*)&Qs[d * 68 + ty * 4];
            float4 kb = *(const float4*)&Ks[d * 68 + tx * 4];
            s[0][0] += qa.x*kb.x; s[0][1] += qa.x*kb.y; s[0][2] += qa.x*kb.z; s[0][3] += qa.x*kb.w;
            s[1][0] += qa.y*kb.x; s[1][1] += qa.y*kb.y; s[1][2] += qa.y*kb.z; s[1][3] += qa.y*kb.w;
            s[2][0] += qa.z*kb.x; s[2][1] += qa.z*kb.y; s[2][2] += qa.z*kb.z; s[2][3] += qa.z*kb.w;
            s[3][0] += qa.w*kb.x; s[3][1] += qa.w*kb.y; s[3][2] += qa.w*kb.z; s[3][3] += qa.w*kb.w;
        }

        if (kt == blockIdx.x) {   // diagonal tile: mask j > i
#pragma unroll
            for (int r = 0; r < 4; r++)
#pragma unroll
                for (int c = 0; c < 4; c++)
                    if (ty*4 + r < tx*4 + c) s[r][c] = -CUDART_INF_F;
        }

        // Online softmax (rows spread over 16 lanes sharing ty)
#pragma unroll
        for (int r = 0; r < 4; r++) {
            float rm = fmaxf(fmaxf(s[r][0], s[r][1]), fmaxf(s[r][2], s[r][3]));
            rm = fmaxf(rm, __shfl_xor_sync(0xffffffffu, rm, 1));
            rm = fmaxf(rm, __shfl_xor_sync(0xffffffffu, rm, 2));
            rm = fmaxf(rm, __shfl_xor_sync(0xffffffffu, rm, 4));
            rm = fmaxf(rm, __shfl_xor_sync(0xffffffffu, rm, 8));
            float mn   = fmaxf(m_i[r], rm);
            float corr = __expf(m_i[r] - mn);
            float rs = 0.f;
#pragma unroll
            for (int c = 0; c < 4; c++) {
                float p = __expf(s[r][c] - mn);
                s[r][c] = p;
                rs += p;
            }
            rs += __shfl_xor_sync(0xffffffffu, rs, 1);
            rs += __shfl_xor_sync(0xffffffffu, rs, 2);
            rs += __shfl_xor_sync(0xffffffffu, rs, 4);
            rs += __shfl_xor_sync(0xffffffffu, rs, 8);
            l_i[r] = l_i[r] * corr + rs;
            m_i[r] = mn;
#pragma unroll
            for (int c = 0; c < 8; c++) oa[r][c] *= corr;
        }

        // Share P
#pragma unroll
        for (int r = 0; r < 4; r++)
#pragma unroll
            for (int c = 0; c < 4; c++)
                Ps[(ty*4 + r) * 68 + tx*4 + c] = s[r][c];
        __syncthreads();

        // O += P V  (rows ty*4..+3, cols tx*8..+7)
#pragma unroll 4
        for (int j = 0; j < 64; j++) {
            float p0 = Ps[(ty*4 + 0) * 68 + j];
            float p1 = Ps[(ty*4 + 1) * 68 + j];
            float p2 = Ps[(ty*4 + 2) * 68 + j];
            float p3 = Ps[(ty*4 + 3) * 68 + j];
            float4 v0 = *(const float4*)&Vs[j * 128 + tx*8];
            float4 v1 = *(const float4*)&Vs[j * 128 + tx*8 + 4];
            oa[0][0] += p0*v0.x; oa[0][1] += p0*v0.y; oa[0][2] += p0*v0.z; oa[0][3] += p0*v0.w;
            oa[0][4] += p0*v1.x; oa[0][5] += p0*v1.y; oa[0][6] += p0*v1.z; oa[0][7] += p0*v1.w;
            oa[1][0] += p1*v0.x; oa[1][1] += p1*v0.y; oa[1][2] += p1*v0.z; oa[1][3] += p1*v0.w;
            oa[1][4] += p1*v1.x; oa[1][5] += p1*v1.y; oa[1][6] += p1*v1.z; oa[1][7] += p1*v1.w;
            oa[2][0] += p2*v0.x; oa[2][1] += p2*v0.y; oa[2][2] += p2*v0.z; oa[2][3] += p2*v0.w;
            oa[2][4] += p2*v1.x; oa[2][5] += p2*v1.y; oa[2][6] += p2*v1.z; oa[2][7] += p2*v1.w;
            oa[3][0] += p3*v0.x; oa[3][1] += p3*v0.y; oa[3][2] += p3*v0.z; oa[3][3] += p3*v0.w;
            oa[3][4] += p3*v1.x; oa[3][5] += p3*v1.y; oa[3][6] += p3*v1.z; oa[3][7] += p3*v1.w;
        }
    }

    // Finalize: divide by l, write to g_o [b][t][h*HD+d]
    const int b = bh >> 4;
    const int h = bh & 15;
    float* og = g_o + ((size_t)b * Tz + q0) * Dz + h * HDz + tx * 8;
#pragma unroll
    for (int r = 0; r < 4; r++) {
        float inv = 1.0f / l_i[r];
        float4 o0 = make_float4(oa[r][0]*inv, oa[r][1]*inv, oa[r][2]*inv, oa[r][3]*inv);
        float4 o1 = make_float4(oa[r][4]*inv, oa[r][5]*inv, oa[r][6]*inv, oa[r][7]*inv);
        *(float4*)(og + (size_t)(ty*4 + r) * Dz)     = o0;
        *(float4*)(og + (size_t)(ty*4 + r) * Dz + 4) = o1;
    }
}

// ---------------------------------------------------------------------------
extern "C" void kernel_launch(void* const* d_in, const int* in_sizes, int n_in,
                              void* d_out, int out_size)
{
    const float* x     = (const float*)d_in[0];
    const float* cosT  = (const float*)d_in[1];
    const float* sinT  = (const float*)d_in[2];
    const float* w_qkv = (const float*)d_in[3];
    const float* w_out = (const float*)d_in[4];
    float* out = (float*)d_out;

    cudaFuncSetAttribute(attn_kernel,
                         cudaFuncAttributeMaxDynamicSharedMemorySize, ATTN_SMEM);

    // 1. QKV projection + scatter (q,k d-major; v t-major)
    sgemm_nt<0><<<dim3(48, 64), 256>>>(x, w_qkv, nullptr, Mz, 3*Dz, Dz);

    // 2. RoPE in place on q,k
    rope_kernel<<<(BHz * 64 * Tz) / 256, 256>>>(cosT, sinT);

    // 3. Causal flash attention
    attn_kernel<<<dim3(Tz / 64, BHz), 256, ATTN_SMEM>>>();

    // 4. Output projection
    sgemm_nt<1><<<dim3(16, 64), 256>>>(nullptr, w_out, out, Mz, Dz, Dz);
}

// round 4
// speedup vs baseline: 1.5991x; 1.5991x over previous
#include <cuda_runtime.h>
#include <cuda_bf16.h>
#include <math_constants.h>
#include <cstdint>

// Problem constants
#define Bz  4
#define Tz  2048
#define Dz  2048
#define Hz  16
#define HDz 128
#define BHz (Bz*Hz)          // 64
#define Mz  (Bz*Tz)          // 8192

// ---------------------------------------------------------------------------
// Global scratch (device globals: allocation-free per harness rules)
// ---------------------------------------------------------------------------
__device__ float g_qT[(size_t)BHz * HDz * Tz];   // [bh][d][t]
__device__ float g_kT[(size_t)BHz * HDz * Tz];   // [bh][d][t]
__device__ float g_v [(size_t)BHz * Tz * HDz];   // [bh][t][d]
__device__ float g_o [(size_t)Mz * Dz];          // [b*t][h*HD+d]

// bf16 hi/lo split copies for tensor-core GEMMs
__device__ __nv_bfloat16 g_xh [(size_t)Mz * Dz];
__device__ __nv_bfloat16 g_xl [(size_t)Mz * Dz];
__device__ __nv_bfloat16 g_wqh[(size_t)3 * Dz * Dz];
__device__ __nv_bfloat16 g_wql[(size_t)3 * Dz * Dz];
__device__ __nv_bfloat16 g_woh[(size_t)Dz * Dz];
__device__ __nv_bfloat16 g_wol[(size_t)Dz * Dz];
__device__ __nv_bfloat16 g_oh [(size_t)Mz * Dz];
__device__ __nv_bfloat16 g_ol [(size_t)Mz * Dz];

// ---------------------------------------------------------------------------
// PTX helpers (base sm_100 — NO 'a'-gated instructions)
// ---------------------------------------------------------------------------
__device__ __forceinline__ uint32_t smem_u32(const void* p) {
    uint32_t a;
    asm("{ .reg .u64 t; cvta.to.shared.u64 t, %1; cvt.u32.u64 %0, t; }"
        : "=r"(a) : "l"(p));
    return a;
}

#define CP16(saddr, gptr) \
    asm volatile("cp.async.cg.shared.global [%0], [%1], 16;" \
                 :: "r"(saddr), "l"(gptr) : "memory")
#define CP_COMMIT() asm volatile("cp.async.commit_group;" ::: "memory")
#define CP_WAIT(n)  asm volatile("cp.async.wait_group %0;" :: "n"(n) : "memory")

#define LDSM4(r0, r1, r2, r3, a) \
    asm volatile("ldmatrix.sync.aligned.m8n8.x4.shared.b16 {%0,%1,%2,%3}, [%4];" \
                 : "=r"(r0), "=r"(r1), "=r"(r2), "=r"(r3) : "r"(a))

#define MMA_BF16(d, a, b) \
    asm volatile("mma.sync.aligned.m16n8k16.row.col.f32.bf16.bf16.f32 " \
                 "{%0,%1,%2,%3}, {%4,%5,%6,%7}, {%8,%9}, {%0,%1,%2,%3};" \
                 : "+f"((d)[0]), "+f"((d)[1]), "+f"((d)[2]), "+f"((d)[3]) \
                 : "r"((a)[0]), "r"((a)[1]), "r"((a)[2]), "r"((a)[3]), \
                   "r"((b)[0]), "r"((b)[1]))

// ---------------------------------------------------------------------------
// Split fp32 -> bf16 hi + bf16 lo.  W selects destination arrays.
// W=0: x -> g_xh/g_xl   W=1: w_qkv -> g_wqh/g_wql
// W=2: w_out -> g_woh/g_wol   W=3: g_o -> g_oh/g_ol
// ---------------------------------------------------------------------------
template<int W>
__global__ void split_kernel(const float* __restrict__ src)
{
    __nv_bfloat16* hi; __nv_bfloat16* lo; const float* s;
    if (W == 0)      { hi = g_xh;  lo = g_xl;  s = src; }
    else if (W == 1) { hi = g_wqh; lo = g_wql; s = src; }
    else if (W == 2) { hi = g_woh; lo = g_wol; s = src; }
    else             { hi = g_oh;  lo = g_ol;  s = g_o; }

    size_t i = ((size_t)blockIdx.x * 256 + threadIdx.x) * 4;
    float4 v = *(const float4*)(s + i);
    __nv_bfloat16 h0 = __float2bfloat16_rn(v.x);
    __nv_bfloat16 h1 = __float2bfloat16_rn(v.y);
    __nv_bfloat16 h2 = __float2bfloat16_rn(v.z);
    __nv_bfloat16 h3 = __float2bfloat16_rn(v.w);
    __nv_bfloat162 H0; H0.x = h0; H0.y = h1;
    __nv_bfloat162 H1; H1.x = h2; H1.y = h3;
    *(__nv_bfloat162*)(hi + i)     = H0;
    *(__nv_bfloat162*)(hi + i + 2) = H1;
    __nv_bfloat162 L0, L1;
    L0.x = __float2bfloat16_rn(v.x - __bfloat162float(h0));
    L0.y = __float2bfloat16_rn(v.y - __bfloat162float(h1));
    L1.x = __float2bfloat16_rn(v.z - __bfloat162float(h2));
    L1.y = __float2bfloat16_rn(v.w - __bfloat162float(h3));
    *(__nv_bfloat162*)(lo + i)     = L0;
    *(__nv_bfloat162*)(lo + i + 2) = L1;
}

// ---------------------------------------------------------------------------
// bf16x3 tensor-core GEMM.  C = A * B^T (both [rows, 2048] row-major, split
// into hi/lo bf16).  128x128 CTA tile, 8 warps (2x4), warp tile 64x32,
// K-chunk 32, 3-stage cp.async pipeline.
// Stage buffer rows are padded to 80B (5x16B chunks): (5r+c) mod 8 is a
// permutation over 8 rows -> conflict-free ldmatrix, no XOR swizzle needed.
// MODE 0: A=x(split), B=w_qkv(split), epilogue scatters to g_qT/g_kT/g_v.
// MODE 1: A=g_o(split), B=w_out(split), epilogue writes C.
// ---------------------------------------------------------------------------
#define RPITCH   80
#define SBUF     (128 * RPITCH)          // 10240 B per buffer
#define STAGEB   (4 * SBUF)              // Ahi,Alo,Bhi,Blo = 40960 B
#define NSTAGE   3
#define GSMEM    (NSTAGE * STAGEB)       // 122880 B (epilogue reuses: needs 67.6KB)

template<int MODE>
__global__ __launch_bounds__(256, 1)
void mma_gemm(float* __restrict__ C)
{
    extern __shared__ char smc[];
    const uint32_t sb = smem_u32(smc);
    const int tid = threadIdx.x;
    const int wid = tid >> 5;
    const int lid = tid & 31;
    const int wm  = wid & 1;          // 0..1  (64 rows each)
    const int wn  = wid >> 1;         // 0..3  (32 cols each)
    const int m0  = blockIdx.y * 128;
    const int n0  = blockIdx.x * 128;

    const __nv_bfloat16* Ah = ((MODE == 0) ? g_xh  : g_oh ) + (size_t)m0 * 2048;
    const __nv_bfloat16* Al = ((MODE == 0) ? g_xl  : g_ol ) + (size_t)m0 * 2048;
    const __nv_bfloat16* Bh = ((MODE == 0) ? g_wqh : g_woh) + (size_t)n0 * 2048;
    const __nv_bfloat16* Bl = ((MODE == 0) ? g_wql : g_wol) + (size_t)n0 * 2048;

    // cp.async thread mapping: row = tid>>1, two 16B chunks per thread
    const int crow = tid >> 1;
    const int cc0  = (tid & 1) * 2;
    const uint32_t soff = (uint32_t)(crow * RPITCH + cc0 * 16);

    float d[4][4][4];
#pragma unroll
    for (int i = 0; i < 4; i++)
#pragma unroll
        for (int j = 0; j < 4; j++)
#pragma unroll
            for (int k = 0; k < 4; k++) d[i][j][k] = 0.f;

    // Prologue: fill 3 stages
#pragma unroll
    for (int s = 0; s < NSTAGE; s++) {
        const uint32_t st = sb + s * STAGEB;
        const size_t gi = (size_t)crow * 2048 + s * 32 + cc0 * 8;
        CP16(st + soff,                Ah + gi);
        CP16(st + soff + 16,           Ah + gi + 8);
        CP16(st + SBUF + soff,         Al + gi);
        CP16(st + SBUF + soff + 16,    Al + gi + 8);
        CP16(st + 2*SBUF + soff,       Bh + gi);
        CP16(st + 2*SBUF + soff + 16,  Bh + gi + 8);
        CP16(st + 3*SBUF + soff,       Bl + gi);
        CP16(st + 3*SBUF + soff + 16,  Bl + gi + 8);
        CP_COMMIT();
    }

    const int q  = lid >> 3;          // ldmatrix quadrant group
    const int r8 = lid & 7;
    // A quadrant address pieces
    const int arow = wm * 64 + (q & 1) * 8 + r8;
    // B quadrant address pieces
    const int bfr  = q >> 1;          // frag within x4 pair
    const int bch  = q & 1;           // k-chunk half
    const int brow0 = wn * 32 + bfr * 8 + r8;

    for (int c = 0; c < 64; ++c) {
        CP_WAIT(2);
        __syncthreads();
        const uint32_t st  = sb + (c % NSTAGE) * STAGEB;
        const uint32_t sA  = st;
        const uint32_t sAl = st + SBUF;
        const uint32_t sB  = st + 2 * SBUF;
        const uint32_t sBl = st + 3 * SBUF;

#pragma unroll
        for (int kk = 0; kk < 2; ++kk) {
            const int ck = kk * 2;                 // chunk base within row
            uint32_t ah[4][4], al[4][4], bh[4][2], bl[4][2];
            const uint32_t aoff = (uint32_t)(arow * RPITCH + (ck + (q >> 1)) * 16);
#pragma unroll
            for (int mi = 0; mi < 4; ++mi)
                LDSM4(ah[mi][0], ah[mi][1], ah[mi][2], ah[mi][3],
                      sA + aoff + mi * 16 * RPITCH);
#pragma unroll
            for (int mi = 0; mi < 4; ++mi)
                LDSM4(al[mi][0], al[mi][1], al[mi][2], al[mi][3],
                      sAl + aoff + mi * 16 * RPITCH);

            const uint32_t boff = (uint32_t)(brow0 * RPITCH + (ck + bch) * 16);
            {
                uint32_t t0,t1,t2,t3;
                LDSM4(t0,t1,t2,t3, sB + boff);
                bh[0][0]=t0; bh[0][1]=t1; bh[1][0]=t2; bh[1][1]=t3;
                LDSM4(t0,t1,t2,t3, sB + boff + 16 * RPITCH);
                bh[2][0]=t0; bh[2][1]=t1; bh[3][0]=t2; bh[3][1]=t3;
                LDSM4(t0,t1,t2,t3, sBl + boff);
                bl[0][0]=t0; bl[0][1]=t1; bl[1][0]=t2; bl[1][1]=t3;
                LDSM4(t0,t1,t2,t3, sBl + boff + 16 * RPITCH);
                bl[2][0]=t0; bl[2][1]=t1; bl[3][0]=t2; bl[3][1]=t3;
            }
            // hi*hi, then lo*hi, then hi*lo (reuse distance 16 -> no RAW stall)
#pragma unroll
            for (int mi = 0; mi < 4; ++mi)
#pragma unroll
                for (int ni = 0; ni < 4; ++ni)
                    MMA_BF16(d[mi][ni], ah[mi], bh[ni]);
#pragma unroll
            for (int mi = 0; mi < 4; ++mi)
#pragma unroll
                for (int ni = 0; ni < 4; ++ni)
                    MMA_BF16(d[mi][ni], al[mi], bh[ni]);
#pragma unroll
            for (int mi = 0; mi < 4; ++mi)
#pragma unroll
                for (int ni = 0; ni < 4; ++ni)
                    MMA_BF16(d[mi][ni], ah[mi], bl[ni]);
        }
        __syncthreads();

        const int nc = c + NSTAGE;
        if (nc < 64) {
            const uint32_t ns = sb + (c % NSTAGE) * STAGEB;
            const size_t gi = (size_t)crow * 2048 + nc * 32 + cc0 * 8;
            CP16(ns + soff,               Ah + gi);
            CP16(ns + soff + 16,          Ah + gi + 8);
            CP16(ns + SBUF + soff,        Al + gi);
            CP16(ns + SBUF + soff + 16,   Al + gi + 8);
            CP16(ns + 2*SBUF + soff,      Bh + gi);
            CP16(ns + 2*SBUF + soff + 16, Bh + gi + 8);
            CP16(ns + 3*SBUF + soff,      Bl + gi);
            CP16(ns + 3*SBUF + soff + 16, Bl + gi + 8);
        }
        CP_COMMIT();
    }

    CP_WAIT(0);
    __syncthreads();

    // Stage fp32 tile in SMEM (pitch 132), then coalesced writers
    float* Sf = (float*)smc;
#pragma unroll
    for (int mi = 0; mi < 4; ++mi) {
        const int r0 = wm * 64 + mi * 16 + (lid >> 2);
#pragma unroll
        for (int ni = 0; ni < 4; ++ni) {
            const int c0 = wn * 32 + ni * 8 + (lid & 3) * 2;
            Sf[r0 * 132 + c0]           = d[mi][ni][0];
            Sf[r0 * 132 + c0 + 1]       = d[mi][ni][1];
            Sf[(r0 + 8) * 132 + c0]     = d[mi][ni][2];
            Sf[(r0 + 8) * 132 + c0 + 1] = d[mi][ni][3];
        }
    }
    __syncthreads();

    if (MODE == 1) {
#pragma unroll
        for (int rr = 0; rr < 16; ++rr) {
            const int row = wid * 16 + rr;
            float4 v = *(const float4*)&Sf[row * 132 + lid * 4];
            *(float4*)(C + (size_t)(m0 + row) * 2048 + n0 + lid * 4) = v;
        }
    } else {
        const int qmode = n0 >> 11;              // 0:q 1:k 2:v
        const int h     = (n0 & 2047) >> 7;
        const int b     = m0 >> 11;
        const int t0    = m0 & 2047;
        const int bh    = b * Hz + h;
        if (qmode == 2) {
            float* dst = g_v + (size_t)bh * Tz * HDz;
#pragma unroll
            for (int rr = 0; rr < 16; ++rr) {
                const int row = wid * 16 + rr;
                float4 v = *(const float4*)&Sf[row * 132 + lid * 4];
                *(float4*)(dst + (size_t)(t0 + row) * HDz + lid * 4) = v;
            }
        } else {
            float* dst = (qmode == 0) ? g_qT : g_kT;
            const size_t hb = (size_t)bh * HDz;
#pragma unroll
            for (int cc = 0; cc < 16; ++cc) {
                const int dcol = wid * 16 + cc;
#pragma unroll
                for (int rr = 0; rr < 4; ++rr) {
                    const int row = rr * 32 + lid;
                    dst[(hb + dcol) * Tz + t0 + row] = Sf[row * 132 + dcol];
                }
            }
        }
    }
}

// ---------------------------------------------------------------------------
// RoPE in place on g_qT / g_kT (d-major layout; pairs (d, d+64) at fixed t).
// ---------------------------------------------------------------------------
__global__ void rope_kernel(const float* __restrict__ cosT,
                            const float* __restrict__ sinT)
{
    unsigned idx = blockIdx.x * blockDim.x + threadIdx.x;   // < BH*64*T
    int t        = idx & (Tz - 1);
    unsigned r   = idx >> 11;
    int d        = r & 63;
    int bh       = r >> 6;
    size_t base  = ((size_t)bh * HDz + d) * Tz + t;

    float c = cosT[t * HDz + d];
    float s = sinT[t * HDz + d];

    float q1 = g_qT[base], q2 = g_qT[base + (size_t)64 * Tz];
    g_qT[base]                  = q1 * c - q2 * s;
    g_qT[base + (size_t)64*Tz]  = q2 * c + q1 * s;

    float k1 = g_kT[base], k2 = g_kT[base + (size_t)64 * Tz];
    g_kT[base]                  = k1 * c - k2 * s;
    g_kT[base + (size_t)64*Tz]  = k2 * c + k1 * s;
}

// ---------------------------------------------------------------------------
// Causal flash attention, fp32.  BM=BN=64, HD=128, 256 threads (16x16).
// ---------------------------------------------------------------------------
#define ATTN_SMEM ((128*68 + 128*68 + 64*128 + 64*68) * 4)

__global__ __launch_bounds__(256, 1)
void attn_kernel()
{
    extern __shared__ float sm[];
    float* Qs = sm;                    // [128][68]
    float* Ks = Qs + 128 * 68;         // [128][68]
    float* Vs = Ks + 128 * 68;         // [64][128]
    float* Ps = Vs + 64 * 128;         // [64][68]

    const int tid = threadIdx.x;
    const int tx  = tid & 15;
    const int ty  = tid >> 4;
    const int bh  = blockIdx.y;
    const int q0  = blockIdx.x * 64;
    const float scale = 0.08838834764831845f;

    const float* qg = g_qT + (size_t)bh * HDz * Tz + q0;
#pragma unroll
    for (int it = 0; it < 8; it++) {
        int idx = tid + it * 256;
        int d   = idx >> 4;
        int i4  = (idx & 15) << 2;
        float4 v = *(const float4*)(qg + (size_t)d * Tz + i4);
        v.x *= scale; v.y *= scale; v.z *= scale; v.w *= scale;
        *(float4*)&Qs[d * 68 + i4] = v;
    }

    float m_i[4], l_i[4], oa[4][8];
#pragma unroll
    for (int r = 0; r < 4; r++) {
        m_i[r] = -CUDART_INF_F;
        l_i[r] = 0.f;
#pragma unroll
        for (int c = 0; c < 8; c++) oa[r][c] = 0.f;
    }

    const float* kg = g_kT + (size_t)bh * HDz * Tz;
    const float* vg = g_v  + (size_t)bh * Tz * HDz;
    const int ntiles = blockIdx.x + 1;

    for (int kt = 0; kt < ntiles; kt++) {
        const int j0 = kt * 64;
        __syncthreads();
#pragma unroll
        for (int it = 0; it < 8; it++) {
            int idx = tid + it * 256;
            int d   = idx >> 4;
            int i4  = (idx & 15) << 2;
            *(float4*)&Ks[d * 68 + i4] =
                *(const float4*)(kg + (size_t)d * Tz + j0 + i4);
        }
#pragma unroll
        for (int it = 0; it < 8; it++) {
            int idx = tid + it * 256;
            int j   = idx >> 5;
            int ds  = (idx & 31) << 2;
            *(float4*)&Vs[j * 128 + ds] =
                *(const float4*)(vg + (size_t)(j0 + j) * HDz + ds);
        }
        __syncthreads();

        float s[4][4] = {{0.f,0.f,0.f,0.f},{0.f,0.f,0.f,0.f},
                         {0.f,0.f,0.f,0.f},{0.f,0.f,0.f,0.f}};
#pragma unroll 8
        for (int d = 0; d < 128; d++) {
            float4 qa = *(const float4*)&Qs[d * 68 + ty * 4];
            float4 kb = *(const float4*)&Ks[d * 68 + tx * 4];
            s[0][0] += qa.x*kb.x; s[0][1] += qa.x*kb.y; s[0][2] += qa.x*kb.z; s[0][3] += qa.x*kb.w;
            s[1][0] += qa.y*kb.x; s[1][1] += qa.y*kb.y; s[1][2] += qa.y*kb.z; s[1][3] += qa.y*kb.w;
            s[2][0] += qa.z*kb.x; s[2][1] += qa.z*kb.y; s[2][2] += qa.z*kb.z; s[2][3] += qa.z*kb.w;
            s[3][0] += qa.w*kb.x; s[3][1] += qa.w*kb.y; s[3][2] += qa.w*kb.z; s[3][3] += qa.w*kb.w;
        }

        if (kt == blockIdx.x) {
#pragma unroll
            for (int r = 0; r < 4; r++)
#pragma unroll
                for (int c = 0; c < 4; c++)
                    if (ty*4 + r < tx*4 + c) s[r][c] = -CUDART_INF_F;
        }

#pragma unroll
        for (int r = 0; r < 4; r++) {
            float rm = fmaxf(fmaxf(s[r][0], s[r][1]), fmaxf(s[r][2], s[r][3]));
            rm = fmaxf(rm, __shfl_xor_sync(0xffffffffu, rm, 1));
            rm = fmaxf(rm, __shfl_xor_sync(0xffffffffu, rm, 2));
            rm = fmaxf(rm, __shfl_xor_sync(0xffffffffu, rm, 4));
            rm = fmaxf(rm, __shfl_xor_sync(0xffffffffu, rm, 8));
            float mn   = fmaxf(m_i[r], rm);
            float corr = __expf(m_i[r] - mn);
            float rs = 0.f;
#pragma unroll
            for (int c = 0; c < 4; c++) {
                float p = __expf(s[r][c] - mn);
                s[r][c] = p;
                rs += p;
            }
            rs += __shfl_xor_sync(0xffffffffu, rs, 1);
            rs += __shfl_xor_sync(0xffffffffu, rs, 2);
            rs += __shfl_xor_sync(0xffffffffu, rs, 4);
            rs += __shfl_xor_sync(0xffffffffu, rs, 8);
            l_i[r] = l_i[r] * corr + rs;
            m_i[r] = mn;
#pragma unroll
            for (int c = 0; c < 8; c++) oa[r][c] *= corr;
        }

#pragma unroll
        for (int r = 0; r < 4; r++)
#pragma unroll
            for (int c = 0; c < 4; c++)
                Ps[(ty*4 + r) * 68 + tx*4 + c] = s[r][c];
        __syncthreads();

#pragma unroll 4
        for (int j = 0; j < 64; j++) {
            float p0 = Ps[(ty*4 + 0) * 68 + j];
            float p1 = Ps[(ty*4 + 1) * 68 + j];
            float p2 = Ps[(ty*4 + 2) * 68 + j];
            float p3 = Ps[(ty*4 + 3) * 68 + j];
            float4 v0 = *(const float4*)&Vs[j * 128 + tx*8];
            float4 v1 = *(const float4*)&Vs[j * 128 + tx*8 + 4];
            oa[0][0] += p0*v0.x; oa[0][1] += p0*v0.y; oa[0][2] += p0*v0.z; oa[0][3] += p0*v0.w;
            oa[0][4] += p0*v1.x; oa[0][5] += p0*v1.y; oa[0][6] += p0*v1.z; oa[0][7] += p0*v1.w;
            oa[1][0] += p1*v0.x; oa[1][1] += p1*v0.y; oa[1][2] += p1*v0.z; oa[1][3] += p1*v0.w;
            oa[1][4] += p1*v1.x; oa[1][5] += p1*v1.y; oa[1][6] += p1*v1.z; oa[1][7] += p1*v1.w;
            oa[2][0] += p2*v0.x; oa[2][1] += p2*v0.y; oa[2][2] += p2*v0.z; oa[2][3] += p2*v0.w;
            oa[2][4] += p2*v1.x; oa[2][5] += p2*v1.y; oa[2][6] += p2*v1.z; oa[2][7] += p2*v1.w;
            oa[3][0] += p3*v0.x; oa[3][1] += p3*v0.y; oa[3][2] += p3*v0.z; oa[3][3] += p3*v0.w;
            oa[3][4] += p3*v1.x; oa[3][5] += p3*v1.y; oa[3][6] += p3*v1.z; oa[3][7] += p3*v1.w;
        }
    }

    const int b = bh >> 4;
    const int h = bh & 15;
    float* og = g_o + ((size_t)b * Tz + q0) * Dz + h * HDz + tx * 8;
#pragma unroll
    for (int r = 0; r < 4; r++) {
        float inv = 1.0f / l_i[r];
        float4 o0 = make_float4(oa[r][0]*inv, oa[r][1]*inv, oa[r][2]*inv, oa[r][3]*inv);
        float4 o1 = make_float4(oa[r][4]*inv, oa[r][5]*inv, oa[r][6]*inv, oa[r][7]*inv);
        *(float4*)(og + (size_t)(ty*4 + r) * Dz)     = o0;
        *(float4*)(og + (size_t)(ty*4 + r) * Dz + 4) = o1;
    }
}

// ---------------------------------------------------------------------------
extern "C" void kernel_launch(void* const* d_in, const int* in_sizes, int n_in,
                              void* d_out, int out_size)
{
    const float* x     = (const float*)d_in[0];
    const float* cosT  = (const float*)d_in[1];
    const float* sinT  = (const float*)d_in[2];
    const float* w_qkv = (const float*)d_in[3];
    const float* w_out = (const float*)d_in[4];
    float* out = (float*)d_out;

    cudaFuncSetAttribute(mma_gemm<0>,
                         cudaFuncAttributeMaxDynamicSharedMemorySize, GSMEM);
    cudaFuncSetAttribute(mma_gemm<1>,
                         cudaFuncAttributeMaxDynamicSharedMemorySize, GSMEM);
    cudaFuncSetAttribute(attn_kernel,
                         cudaFuncAttributeMaxDynamicSharedMemorySize, ATTN_SMEM);

    // 0. Split inputs to bf16 hi/lo
    split_kernel<0><<<(Mz * Dz) / 1024, 256>>>(x);         // x
    split_kernel<1><<<(3 * Dz * Dz) / 1024, 256>>>(w_qkv); // w_qkv
    split_kernel<2><<<(Dz * Dz) / 1024, 256>>>(w_out);     // w_out

    // 1. QKV projection (bf16x3 tensor cores) + scatter
    mma_gemm<0><<<dim3(48, 64), 256, GSMEM>>>(nullptr);

    // 2. RoPE in place on q,k
    rope_kernel<<<(BHz * 64 * Tz) / 256, 256>>>(cosT, sinT);

    // 3. Causal flash attention (fp32)
    attn_kernel<<<dim3(Tz / 64, BHz), 256, ATTN_SMEM>>>();

    // 4. Split attention output, then output projection (bf16x3)
    split_kernel<3><<<(Mz * Dz) / 1024, 256>>>(nullptr);
    mma_gemm<1><<<dim3(16, 64), 256, GSMEM>>>(out);
}

// round 5
// speedup vs baseline: 2.4393x; 1.5254x over previous
#include <cuda_runtime.h>
#include <cuda_bf16.h>
#include <math_constants.h>
#include <cstdint>

// Problem constants
#define Bz  4
#define Tz  2048
#define Dz  2048
#define Hz  16
#define HDz 128
#define BHz (Bz*Hz)          // 64
#define Mz  (Bz*Tz)          // 8192

// ---------------------------------------------------------------------------
// Global scratch (device globals: allocation-free per harness rules)
// ---------------------------------------------------------------------------
__device__ float g_qf[(size_t)BHz * Tz * HDz];   // [bh][t][d] fp32 (pre-rope)
__device__ float g_kf[(size_t)BHz * Tz * HDz];

__device__ __nv_bfloat16 g_qh[(size_t)BHz * Tz * HDz];  // post-rope, scaled, hi/lo
__device__ __nv_bfloat16 g_ql[(size_t)BHz * Tz * HDz];
__device__ __nv_bfloat16 g_kh[(size_t)BHz * Tz * HDz];
__device__ __nv_bfloat16 g_kl[(size_t)BHz * Tz * HDz];
__device__ __nv_bfloat16 g_vh[(size_t)BHz * Tz * HDz];
__device__ __nv_bfloat16 g_vl[(size_t)BHz * Tz * HDz];

__device__ __nv_bfloat16 g_xh [(size_t)Mz * Dz];
__device__ __nv_bfloat16 g_xl [(size_t)Mz * Dz];
__device__ __nv_bfloat16 g_wqh[(size_t)3 * Dz * Dz];
__device__ __nv_bfloat16 g_wql[(size_t)3 * Dz * Dz];
__device__ __nv_bfloat16 g_woh[(size_t)Dz * Dz];
__device__ __nv_bfloat16 g_wol[(size_t)Dz * Dz];
__device__ __nv_bfloat16 g_oh [(size_t)Mz * Dz];   // attention out hi/lo
__device__ __nv_bfloat16 g_ol [(size_t)Mz * Dz];

// ---------------------------------------------------------------------------
// PTX helpers (base sm_100 — NO 'a'-gated instructions)
// ---------------------------------------------------------------------------
__device__ __forceinline__ uint32_t smem_u32(const void* p) {
    uint32_t a;
    asm("{ .reg .u64 t; cvta.to.shared.u64 t, %1; cvt.u32.u64 %0, t; }"
        : "=r"(a) : "l"(p));
    return a;
}

#define CP16(saddr, gptr) \
    asm volatile("cp.async.cg.shared.global [%0], [%1], 16;" \
                 :: "r"(saddr), "l"(gptr) : "memory")
#define CP_COMMIT() asm volatile("cp.async.commit_group;" ::: "memory")
#define CP_WAIT(n)  asm volatile("cp.async.wait_group %0;" :: "n"(n) : "memory")

#define LDSM4(r0, r1, r2, r3, a) \
    asm volatile("ldmatrix.sync.aligned.m8n8.x4.shared.b16 {%0,%1,%2,%3}, [%4];" \
                 : "=r"(r0), "=r"(r1), "=r"(r2), "=r"(r3) : "r"(a))
#define LDSM4T(r0, r1, r2, r3, a) \
    asm volatile("ldmatrix.sync.aligned.m8n8.x4.trans.shared.b16 {%0,%1,%2,%3}, [%4];" \
                 : "=r"(r0), "=r"(r1), "=r"(r2), "=r"(r3) : "r"(a))

#define MMA_BF16(d, a, b) \
    asm volatile("mma.sync.aligned.m16n8k16.row.col.f32.bf16.bf16.f32 " \
                 "{%0,%1,%2,%3}, {%4,%5,%6,%7}, {%8,%9}, {%0,%1,%2,%3};" \
                 : "+f"((d)[0]), "+f"((d)[1]), "+f"((d)[2]), "+f"((d)[3]) \
                 : "r"((a)[0]), "r"((a)[1]), "r"((a)[2]), "r"((a)[3]), \
                   "r"((b)[0]), "r"((b)[1]))

#define MMA4(d, a0, a1, a2, a3, b0, b1) \
    asm volatile("mma.sync.aligned.m16n8k16.row.col.f32.bf16.bf16.f32 " \
                 "{%0,%1,%2,%3}, {%4,%5,%6,%7}, {%8,%9}, {%0,%1,%2,%3};" \
                 : "+f"((d)[0]), "+f"((d)[1]), "+f"((d)[2]), "+f"((d)[3]) \
                 : "r"(a0), "r"(a1), "r"(a2), "r"(a3), "r"(b0), "r"(b1))

// Split pair of floats into packed bf16 hi + bf16 lo (residual)
__device__ __forceinline__ void split2(float x, float y, uint32_t& hi, uint32_t& lo) {
    __nv_bfloat16 hx = __float2bfloat16_rn(x);
    __nv_bfloat16 hy = __float2bfloat16_rn(y);
    __nv_bfloat162 H; H.x = hx; H.y = hy;
    hi = *(uint32_t*)&H;
    __nv_bfloat162 L;
    L.x = __float2bfloat16_rn(x - __bfloat162float(hx));
    L.y = __float2bfloat16_rn(y - __bfloat162float(hy));
    lo = *(uint32_t*)&L;
}

// ---------------------------------------------------------------------------
// Split fp32 -> bf16 hi + lo.  W=0: x, W=1: w_qkv, W=2: w_out.
// ---------------------------------------------------------------------------
template<int W>
__global__ void split_kernel(const float* __restrict__ src)
{
    __nv_bfloat16* hi; __nv_bfloat16* lo;
    if (W == 0)      { hi = g_xh;  lo = g_xl;  }
    else if (W == 1) { hi = g_wqh; lo = g_wql; }
    else             { hi = g_woh; lo = g_wol; }

    size_t i = ((size_t)blockIdx.x * 256 + threadIdx.x) * 4;
    float4 v = *(const float4*)(src + i);
    uint32_t h0, l0, h1, l1;
    split2(v.x, v.y, h0, l0);
    split2(v.z, v.w, h1, l1);
    *(uint32_t*)(hi + i)     = h0;
    *(uint32_t*)(hi + i + 2) = h1;
    *(uint32_t*)(lo + i)     = l0;
    *(uint32_t*)(lo + i + 2) = l1;
}

// ---------------------------------------------------------------------------
// bf16x3 tensor-core GEMM.  C = A * B^T.  128x128 CTA tile, 8 warps (2x4),
// warp tile 64x32, K-chunk 32, 3-stage cp.async pipeline.  RPITCH=80.
// MODE 0: A=x, B=w_qkv; epilogue: q,k -> fp32 [bh][t][d]; v -> bf16 hi/lo.
// MODE 1: A=g_oh/g_ol, B=w_out; epilogue writes C.
// ---------------------------------------------------------------------------
#define RPITCH   80
#define SBUF     (128 * RPITCH)
#define STAGEB   (4 * SBUF)
#define NSTAGE   3
#define GSMEM    (NSTAGE * STAGEB)

template<int MODE>
__global__ __launch_bounds__(256, 1)
void mma_gemm(float* __restrict__ C)
{
    extern __shared__ char smc[];
    const uint32_t sb = smem_u32(smc);
    const int tid = threadIdx.x;
    const int wid = tid >> 5;
    const int lid = tid & 31;
    const int wm  = wid & 1;
    const int wn  = wid >> 1;
    const int m0  = blockIdx.y * 128;
    const int n0  = blockIdx.x * 128;

    const __nv_bfloat16* Ah = ((MODE == 0) ? g_xh  : g_oh ) + (size_t)m0 * 2048;
    const __nv_bfloat16* Al = ((MODE == 0) ? g_xl  : g_ol ) + (size_t)m0 * 2048;
    const __nv_bfloat16* Bh = ((MODE == 0) ? g_wqh : g_woh) + (size_t)n0 * 2048;
    const __nv_bfloat16* Bl = ((MODE == 0) ? g_wql : g_wol) + (size_t)n0 * 2048;

    const int crow = tid >> 1;
    const int cc0  = (tid & 1) * 2;
    const uint32_t soff = (uint32_t)(crow * RPITCH + cc0 * 16);

    float d[4][4][4];
#pragma unroll
    for (int i = 0; i < 4; i++)
#pragma unroll
        for (int j = 0; j < 4; j++)
#pragma unroll
            for (int k = 0; k < 4; k++) d[i][j][k] = 0.f;

#pragma unroll
    for (int s = 0; s < NSTAGE; s++) {
        const uint32_t st = sb + s * STAGEB;
        const size_t gi = (size_t)crow * 2048 + s * 32 + cc0 * 8;
        CP16(st + soff,                Ah + gi);
        CP16(st + soff + 16,           Ah + gi + 8);
        CP16(st + SBUF + soff,         Al + gi);
        CP16(st + SBUF + soff + 16,    Al + gi + 8);
        CP16(st + 2*SBUF + soff,       Bh + gi);
        CP16(st + 2*SBUF + soff + 16,  Bh + gi + 8);
        CP16(st + 3*SBUF + soff,       Bl + gi);
        CP16(st + 3*SBUF + soff + 16,  Bl + gi + 8);
        CP_COMMIT();
    }

    const int q  = lid >> 3;
    const int r8 = lid & 7;
    const int arow = wm * 64 + (q & 1) * 8 + r8;
    const int bfr  = q >> 1;
    const int bch  = q & 1;
    const int brow0 = wn * 32 + bfr * 8 + r8;

    for (int c = 0; c < 64; ++c) {
        CP_WAIT(2);
        __syncthreads();
        const uint32_t st  = sb + (c % NSTAGE) * STAGEB;
        const uint32_t sA  = st;
        const uint32_t sAl = st + SBUF;
        const uint32_t sB  = st + 2 * SBUF;
        const uint32_t sBl = st + 3 * SBUF;

#pragma unroll
        for (int kk = 0; kk < 2; ++kk) {
            const int ck = kk * 2;
            uint32_t ah[4][4], al[4][4], bh[4][2], bl[4][2];
            const uint32_t aoff = (uint32_t)(arow * RPITCH + (ck + (q >> 1)) * 16);
#pragma unroll
            for (int mi = 0; mi < 4; ++mi)
                LDSM4(ah[mi][0], ah[mi][1], ah[mi][2], ah[mi][3],
                      sA + aoff + mi * 16 * RPITCH);
#pragma unroll
            for (int mi = 0; mi < 4; ++mi)
                LDSM4(al[mi][0], al[mi][1], al[mi][2], al[mi][3],
                      sAl + aoff + mi * 16 * RPITCH);

            const uint32_t boff = (uint32_t)(brow0 * RPITCH + (ck + bch) * 16);
            {
                uint32_t t0,t1,t2,t3;
                LDSM4(t0,t1,t2,t3, sB + boff);
                bh[0][0]=t0; bh[0][1]=t1; bh[1][0]=t2; bh[1][1]=t3;
                LDSM4(t0,t1,t2,t3, sB + boff + 16 * RPITCH);
                bh[2][0]=t0; bh[2][1]=t1; bh[3][0]=t2; bh[3][1]=t3;
                LDSM4(t0,t1,t2,t3, sBl + boff);
                bl[0][0]=t0; bl[0][1]=t1; bl[1][0]=t2; bl[1][1]=t3;
                LDSM4(t0,t1,t2,t3, sBl + boff + 16 * RPITCH);
                bl[2][0]=t0; bl[2][1]=t1; bl[3][0]=t2; bl[3][1]=t3;
            }
#pragma unroll
            for (int mi = 0; mi < 4; ++mi)
#pragma unroll
                for (int ni = 0; ni < 4; ++ni)
                    MMA_BF16(d[mi][ni], ah[mi], bh[ni]);
#pragma unroll
            for (int mi = 0; mi < 4; ++mi)
#pragma unroll
                for (int ni = 0; ni < 4; ++ni)
                    MMA_BF16(d[mi][ni], al[mi], bh[ni]);
#pragma unroll
            for (int mi = 0; mi < 4; ++mi)
#pragma unroll
                for (int ni = 0; ni < 4; ++ni)
                    MMA_BF16(d[mi][ni], ah[mi], bl[ni]);
        }
        __syncthreads();

        const int nc = c + NSTAGE;
        if (nc < 64) {
            const uint32_t ns = sb + (c % NSTAGE) * STAGEB;
            const size_t gi = (size_t)crow * 2048 + nc * 32 + cc0 * 8;
            CP16(ns + soff,               Ah + gi);
            CP16(ns + soff + 16,          Ah + gi + 8);
            CP16(ns + SBUF + soff,        Al + gi);
            CP16(ns + SBUF + soff + 16,   Al + gi + 8);
            CP16(ns + 2*SBUF + soff,      Bh + gi);
            CP16(ns + 2*SBUF + soff + 16, Bh + gi + 8);
            CP16(ns + 3*SBUF + soff,      Bl + gi);
            CP16(ns + 3*SBUF + soff + 16, Bl + gi + 8);
        }
        CP_COMMIT();
    }

    CP_WAIT(0);
    __syncthreads();

    float* Sf = (float*)smc;
#pragma unroll
    for (int mi = 0; mi < 4; ++mi) {
        const int r0 = wm * 64 + mi * 16 + (lid >> 2);
#pragma unroll
        for (int ni = 0; ni < 4; ++ni) {
            const int c0 = wn * 32 + ni * 8 + (lid & 3) * 2;
            Sf[r0 * 132 + c0]           = d[mi][ni][0];
            Sf[r0 * 132 + c0 + 1]       = d[mi][ni][1];
            Sf[(r0 + 8) * 132 + c0]     = d[mi][ni][2];
            Sf[(r0 + 8) * 132 + c0 + 1] = d[mi][ni][3];
        }
    }
    __syncthreads();

    if (MODE == 1) {
#pragma unroll
        for (int rr = 0; rr < 16; ++rr) {
            const int row = wid * 16 + rr;
            float4 v = *(const float4*)&Sf[row * 132 + lid * 4];
            *(float4*)(C + (size_t)(m0 + row) * 2048 + n0 + lid * 4) = v;
        }
    } else {
        const int qmode = n0 >> 11;              // 0:q 1:k 2:v
        const int h     = (n0 & 2047) >> 7;
        const int b     = m0 >> 11;
        const int t0    = m0 & 2047;
        const int bhx   = b * Hz + h;
        if (qmode <= 1) {
            float* dst = ((qmode == 0) ? g_qf : g_kf)
                       + ((size_t)bhx * Tz + t0) * HDz;
#pragma unroll
            for (int rr = 0; rr < 16; ++rr) {
                const int row = wid * 16 + rr;
                float4 v = *(const float4*)&Sf[row * 132 + lid * 4];
                *(float4*)(dst + (size_t)row * HDz + lid * 4) = v;
            }
        } else {
            __nv_bfloat16* dh = g_vh + ((size_t)bhx * Tz + t0) * HDz;
            __nv_bfloat16* dl = g_vl + ((size_t)bhx * Tz + t0) * HDz;
#pragma unroll
            for (int rr = 0; rr < 16; ++rr) {
                const int row = wid * 16 + rr;
                float4 v = *(const float4*)&Sf[row * 132 + lid * 4];
                uint32_t h0, l0, h1, l1;
                split2(v.x, v.y, h0, l0);
                split2(v.z, v.w, h1, l1);
                *(uint32_t*)(dh + (size_t)row * HDz + lid * 4)     = h0;
                *(uint32_t*)(dh + (size_t)row * HDz + lid * 4 + 2) = h1;
                *(uint32_t*)(dl + (size_t)row * HDz + lid * 4)     = l0;
                *(uint32_t*)(dl + (size_t)row * HDz + lid * 4 + 2) = l1;
            }
        }
    }
}

// ---------------------------------------------------------------------------
// RoPE: read fp32 q/k [bh][t][d], rotate pairs (d, d+64), scale q, split to
// bf16 hi/lo [bh][t][d].
// ---------------------------------------------------------------------------
__global__ void rope_kernel(const float* __restrict__ cosT,
                            const float* __restrict__ sinT)
{
    unsigned idx = blockIdx.x * 256 + threadIdx.x;   // < BH*T*64
    int d  = idx & 63;
    int t  = (idx >> 6) & (Tz - 1);
    int bh = idx >> 17;
    size_t base = ((size_t)bh * Tz + t) * HDz + d;

    float c = cosT[t * HDz + d];
    float s = sinT[t * HDz + d];
    const float scale = 0.08838834764831845f;   // 128^-0.5

    float q1 = g_qf[base], q2 = g_qf[base + 64];
    float r1 = (q1 * c - q2 * s) * scale;
    float r2 = (q2 * c + q1 * s) * scale;
    {
        __nv_bfloat16 h1 = __float2bfloat16_rn(r1);
        __nv_bfloat16 h2 = __float2bfloat16_rn(r2);
        g_qh[base]      = h1;
        g_qh[base + 64] = h2;
        g_ql[base]      = __float2bfloat16_rn(r1 - __bfloat162float(h1));
        g_ql[base + 64] = __float2bfloat16_rn(r2 - __bfloat162float(h2));
    }
    float k1 = g_kf[base], k2 = g_kf[base + 64];
    float u1 = k1 * c - k2 * s;
    float u2 = k2 * c + k1 * s;
    {
        __nv_bfloat16 h1 = __float2bfloat16_rn(u1);
        __nv_bfloat16 h2 = __float2bfloat16_rn(u2);
        g_kh[base]      = h1;
        g_kh[base + 64] = h2;
        g_kl[base]      = __float2bfloat16_rn(u1 - __bfloat162float(h1));
        g_kl[base + 64] = __float2bfloat16_rn(u2 - __bfloat162float(h2));
    }
}

// ---------------------------------------------------------------------------
// Causal flash attention on tensor cores (bf16x3).
// BM=128 (8 warps x 16 rows), BN=64, HD=128, 256 threads.
// Q hi/lo resident in SMEM; K/V hi/lo double-buffered cp.async.
// Row pitch 136 bf16 (272B = 17 x 16B chunks -> conflict-free ldmatrix).
// ---------------------------------------------------------------------------
#define AP    136
#define APB   272
#define QSZ   (128 * APB)       // 34816
#define KSZ   (64 * APB)        // 17408
#define ATTN_SMEM2 (2 * QSZ + 2 * 4 * KSZ)   // 208896

__global__ __launch_bounds__(256, 1)
void attn_mma()
{
    extern __shared__ char smc[];
    const uint32_t sb = smem_u32(smc);
    const int tid = threadIdx.x;
    const int wid = tid >> 5;
    const int lid = tid & 31;
    const int bh  = blockIdx.y;
    const int qb  = (int)gridDim.x - 1 - (int)blockIdx.x;  // big blocks first
    const int q0  = qb * 128;
    const int ntiles = 2 * qb + 2;

    const __nv_bfloat16* qh_g = g_qh + ((size_t)bh * Tz + q0) * HDz;
    const __nv_bfloat16* ql_g = g_ql + ((size_t)bh * Tz + q0) * HDz;
    const __nv_bfloat16* kh_g = g_kh + (size_t)bh * Tz * HDz;
    const __nv_bfloat16* kl_g = g_kl + (size_t)bh * Tz * HDz;
    const __nv_bfloat16* vh_g = g_vh + (size_t)bh * Tz * HDz;
    const __nv_bfloat16* vl_g = g_vl + (size_t)bh * Tz * HDz;

    const uint32_t sQh = sb;
    const uint32_t sQl = sb + QSZ;
    const uint32_t sStage = sb + 2 * QSZ;

    // Load Q hi/lo (2048 16B-chunks per array, 8 per thread)
#pragma unroll
    for (int i = 0; i < 8; ++i) {
        int cc = i * 256 + tid;
        int row = cc >> 4, col = cc & 15;
        CP16(sQh + row * APB + col * 16, qh_g + (size_t)row * HDz + col * 8);
    }
#pragma unroll
    for (int i = 0; i < 8; ++i) {
        int cc = i * 256 + tid;
        int row = cc >> 4, col = cc & 15;
        CP16(sQl + row * APB + col * 16, ql_g + (size_t)row * HDz + col * 8);
    }
    CP_COMMIT();

    auto load_stage = [&](int stage, int j0) {
        const uint32_t base = sStage + stage * (4 * KSZ);
        const __nv_bfloat16* gp0 = kh_g + (size_t)j0 * HDz;
        const __nv_bfloat16* gp1 = kl_g + (size_t)j0 * HDz;
        const __nv_bfloat16* gp2 = vh_g + (size_t)j0 * HDz;
        const __nv_bfloat16* gp3 = vl_g + (size_t)j0 * HDz;
#pragma unroll
        for (int i = 0; i < 4; ++i) {
            int cc = i * 256 + tid;              // 0..1023
            int row = cc >> 4, col = cc & 15;
            uint32_t so = (uint32_t)(row * APB + col * 16);
            size_t go = (size_t)row * HDz + col * 8;
            CP16(base + so,           gp0 + go);
            CP16(base + KSZ + so,     gp1 + go);
            CP16(base + 2*KSZ + so,   gp2 + go);
            CP16(base + 3*KSZ + so,   gp3 + go);
        }
    };

    load_stage(0, 0);
    CP_COMMIT();

    // lane constants
    const int qq = lid >> 3;
    const int r8 = lid & 7;
    const int g  = lid >> 2;
    const int t4 = lid & 3;
    const uint32_t qa_off  = (uint32_t)((wid * 16 + (qq & 1) * 8 + r8) * APB);
    const uint32_t ka_row  = (uint32_t)(((qq >> 1) * 8 + r8) * APB);
    const uint32_t va_off  = (uint32_t)((((lid >> 3) & 1) * 8 + (lid & 7)) * APB
                                        + (lid >> 4) * 16);

    float m0v = -1e30f, m1v = -1e30f, l0v = 0.f, l1v = 0.f;
    float o[16][4];
#pragma unroll
    for (int i = 0; i < 16; i++)
#pragma unroll
        for (int j = 0; j < 4; j++) o[i][j] = 0.f;

    for (int kt = 0; kt < ntiles; ++kt) {
        if (kt + 1 < ntiles) {
            load_stage((kt + 1) & 1, (kt + 1) * 64);
            CP_COMMIT();
            CP_WAIT(1);
        } else {
            CP_WAIT(0);
        }
        __syncthreads();

        const uint32_t sK  = sStage + (kt & 1) * (4 * KSZ);
        const uint32_t sKh = sK;
        const uint32_t sKl = sK + KSZ;
        const uint32_t sVh = sK + 2 * KSZ;
        const uint32_t sVl = sK + 3 * KSZ;

        const bool active = !(kt == ntiles - 1 && wid < 4);
        if (active) {
            // ---- S = Q K^T ----
            float sf[8][4];
#pragma unroll
            for (int i = 0; i < 8; i++)
#pragma unroll
                for (int j = 0; j < 4; j++) sf[i][j] = 0.f;

#pragma unroll
            for (int kk = 0; kk < 8; ++kk) {
                const uint32_t acol = (uint32_t)((kk * 2 + (qq >> 1)) * 16);
                const uint32_t kcol = (uint32_t)((kk * 2 + (qq & 1)) * 16);
                uint32_t ah0,ah1,ah2,ah3, al0,al1,al2,al3;
                LDSM4(ah0,ah1,ah2,ah3, sQh + qa_off + acol);
                LDSM4(al0,al1,al2,al3, sQl + qa_off + acol);
#pragma unroll
                for (int h2 = 0; h2 < 2; ++h2) {
                    uint32_t b0h[4], b1h[4], b0l[4], b1l[4];
                    const uint32_t r0 = (uint32_t)((2*h2) * 16 * APB);
                    const uint32_t r1 = (uint32_t)((2*h2 + 1) * 16 * APB);
                    LDSM4(b0h[0],b0h[1],b0h[2],b0h[3], sKh + ka_row + r0 + kcol);
                    LDSM4(b1h[0],b1h[1],b1h[2],b1h[3], sKh + ka_row + r1 + kcol);
                    LDSM4(b0l[0],b0l[1],b0l[2],b0l[3], sKl + ka_row + r0 + kcol);
                    LDSM4(b1l[0],b1l[1],b1l[2],b1l[3], sKl + ka_row + r1 + kcol);
                    MMA4(sf[4*h2+0], ah0,ah1,ah2,ah3, b0h[0], b0h[1]);
                    MMA4(sf[4*h2+1], ah0,ah1,ah2,ah3, b0h[2], b0h[3]);
                    MMA4(sf[4*h2+2], ah0,ah1,ah2,ah3, b1h[0], b1h[1]);
                    MMA4(sf[4*h2+3], ah0,ah1,ah2,ah3, b1h[2], b1h[3]);
                    MMA4(sf[4*h2+0], al0,al1,al2,al3, b0h[0], b0h[1]);
                    MMA4(sf[4*h2+1], al0,al1,al2,al3, b0h[2], b0h[3]);
                    MMA4(sf[4*h2+2], al0,al1,al2,al3, b1h[0], b1h[1]);
                    MMA4(sf[4*h2+3], al0,al1,al2,al3, b1h[2], b1h[3]);
                    MMA4(sf[4*h2+0], ah0,ah1,ah2,ah3, b0l[0], b0l[1]);
                    MMA4(sf[4*h2+1], ah0,ah1,ah2,ah3, b0l[2], b0l[3]);
                    MMA4(sf[4*h2+2], ah0,ah1,ah2,ah3, b1l[0], b1l[1]);
                    MMA4(sf[4*h2+3], ah0,ah1,ah2,ah3, b1l[2], b1l[3]);
                }
            }

            // ---- causal mask ----
            if (kt == ntiles - 2) {
                if (wid < 4) {
                    const int i0 = wid * 16 + g;
                    const int i1 = i0 + 8;
#pragma unroll
                    for (int ns = 0; ns < 8; ++ns) {
                        const int jc = ns * 8 + t4 * 2;
                        if (jc     > i0) sf[ns][0] = -1e30f;
                        if (jc + 1 > i0) sf[ns][1] = -1e30f;
                        if (jc     > i1) sf[ns][2] = -1e30f;
                        if (jc + 1 > i1) sf[ns][3] = -1e30f;
                    }
                }
            } else if (kt == ntiles - 1) {   // wid >= 4 here
                const int i0 = wid * 16 + g - 64;
                const int i1 = i0 + 8;
#pragma unroll
                for (int ns = 0; ns < 8; ++ns) {
                    const int jc = ns * 8 + t4 * 2;
                    if (jc     > i0) sf[ns][0] = -1e30f;
                    if (jc + 1 > i0) sf[ns][1] = -1e30f;
                    if (jc     > i1) sf[ns][2] = -1e30f;
                    if (jc + 1 > i1) sf[ns][3] = -1e30f;
                }
            }

            // ---- online softmax ----
            float rm0 = -1e30f, rm1 = -1e30f;
#pragma unroll
            for (int ns = 0; ns < 8; ++ns) {
                rm0 = fmaxf(rm0, fmaxf(sf[ns][0], sf[ns][1]));
                rm1 = fmaxf(rm1, fmaxf(sf[ns][2], sf[ns][3]));
            }
            rm0 = fmaxf(rm0, __shfl_xor_sync(0xffffffffu, rm0, 1));
            rm0 = fmaxf(rm0, __shfl_xor_sync(0xffffffffu, rm0, 2));
            rm1 = fmaxf(rm1, __shfl_xor_sync(0xffffffffu, rm1, 1));
            rm1 = fmaxf(rm1, __shfl_xor_sync(0xffffffffu, rm1, 2));
            const float mn0 = fmaxf(m0v, rm0);
            const float mn1 = fmaxf(m1v, rm1);
            const float corr0 = __expf(m0v - mn0);
            const float corr1 = __expf(m1v - mn1);
            m0v = mn0; m1v = mn1;
            float rs0 = 0.f, rs1 = 0.f;
#pragma unroll
            for (int ns = 0; ns < 8; ++ns) {
                float p0 = __expf(sf[ns][0] - mn0);
                float p1 = __expf(sf[ns][1] - mn0);
                float p2 = __expf(sf[ns][2] - mn1);
                float p3 = __expf(sf[ns][3] - mn1);
                sf[ns][0] = p0; sf[ns][1] = p1; sf[ns][2] = p2; sf[ns][3] = p3;
                rs0 += p0 + p1; rs1 += p2 + p3;
            }
            rs0 += __shfl_xor_sync(0xffffffffu, rs0, 1);
            rs0 += __shfl_xor_sync(0xffffffffu, rs0, 2);
            rs1 += __shfl_xor_sync(0xffffffffu, rs1, 1);
            rs1 += __shfl_xor_sync(0xffffffffu, rs1, 2);
            l0v = l0v * corr0 + rs0;
            l1v = l1v * corr1 + rs1;
#pragma unroll
            for (int ns = 0; ns < 16; ++ns) {
                o[ns][0] *= corr0; o[ns][1] *= corr0;
                o[ns][2] *= corr1; o[ns][3] *= corr1;
            }

            // ---- P fragments (hi/lo) ----
            uint32_t pah[4][4], pal[4][4];
#pragma unroll
            for (int kk = 0; kk < 4; ++kk) {
                split2(sf[2*kk][0],   sf[2*kk][1],   pah[kk][0], pal[kk][0]);
                split2(sf[2*kk][2],   sf[2*kk][3],   pah[kk][1], pal[kk][1]);
                split2(sf[2*kk+1][0], sf[2*kk+1][1], pah[kk][2], pal[kk][2]);
                split2(sf[2*kk+1][2], sf[2*kk+1][3], pah[kk][3], pal[kk][3]);
            }

            // ---- O += P V ----
#pragma unroll
            for (int kk = 0; kk < 4; ++kk) {
                const uint32_t vrow = (uint32_t)(kk * 16 * APB) + va_off;
#pragma unroll
                for (int dp = 0; dp < 4; ++dp) {
                    uint32_t v0h[4], v1h[4], v0l[4], v1l[4];
                    LDSM4T(v0h[0],v0h[1],v0h[2],v0h[3], sVh + vrow + dp*64);
                    LDSM4T(v1h[0],v1h[1],v1h[2],v1h[3], sVh + vrow + dp*64 + 32);
                    LDSM4T(v0l[0],v0l[1],v0l[2],v0l[3], sVl + vrow + dp*64);
                    LDSM4T(v1l[0],v1l[1],v1l[2],v1l[3], sVl + vrow + dp*64 + 32);
                    MMA4(o[4*dp+0], pah[kk][0],pah[kk][1],pah[kk][2],pah[kk][3], v0h[0], v0h[1]);
                    MMA4(o[4*dp+1], pah[kk][0],pah[kk][1],pah[kk][2],pah[kk][3], v0h[2], v0h[3]);
                    MMA4(o[4*dp+2], pah[kk][0],pah[kk][1],pah[kk][2],pah[kk][3], v1h[0], v1h[1]);
                    MMA4(o[4*dp+3], pah[kk][0],pah[kk][1],pah[kk][2],pah[kk][3], v1h[2], v1h[3]);
                    MMA4(o[4*dp+0], pal[kk][0],pal[kk][1],pal[kk][2],pal[kk][3], v0h[0], v0h[1]);
                    MMA4(o[4*dp+1], pal[kk][0],pal[kk][1],pal[kk][2],pal[kk][3], v0h[2], v0h[3]);
                    MMA4(o[4*dp+2], pal[kk][0],pal[kk][1],pal[kk][2],pal[kk][3], v1h[0], v1h[1]);
                    MMA4(o[4*dp+3], pal[kk][0],pal[kk][1],pal[kk][2],pal[kk][3], v1h[2], v1h[3]);
                    MMA4(o[4*dp+0], pah[kk][0],pah[kk][1],pah[kk][2],pah[kk][3], v0l[0], v0l[1]);
                    MMA4(o[4*dp+1], pah[kk][0],pah[kk][1],pah[kk][2],pah[kk][3], v0l[2], v0l[3]);
                    MMA4(o[4*dp+2], pah[kk][0],pah[kk][1],pah[kk][2],pah[kk][3], v1l[0], v1l[1]);
                    MMA4(o[4*dp+3], pah[kk][0],pah[kk][1],pah[kk][2],pah[kk][3], v1l[2], v1l[3]);
                }
            }
        }
        __syncthreads();
    }

    // ---- finalize + store bf16 hi/lo ----
    const int b  = bh >> 4;
    const int hh = bh & 15;
    const float inv0 = 1.f / l0v;
    const float inv1 = 1.f / l1v;
    const size_t rb0 = ((size_t)b * Tz + q0 + wid * 16 + g) * Dz + hh * HDz;
    const size_t rb1 = rb0 + (size_t)8 * Dz;
#pragma unroll
    for (int ns = 0; ns < 16; ++ns) {
        const int dcol = ns * 8 + t4 * 2;
        uint32_t hi, lo;
        split2(o[ns][0] * inv0, o[ns][1] * inv0, hi, lo);
        *(uint32_t*)(g_oh + rb0 + dcol) = hi;
        *(uint32_t*)(g_ol + rb0 + dcol) = lo;
        split2(o[ns][2] * inv1, o[ns][3] * inv1, hi, lo);
        *(uint32_t*)(g_oh + rb1 + dcol) = hi;
        *(uint32_t*)(g_ol + rb1 + dcol) = lo;
    }
}

// ---------------------------------------------------------------------------
extern "C" void kernel_launch(void* const* d_in, const int* in_sizes, int n_in,
                              void* d_out, int out_size)
{
    const float* x     = (const float*)d_in[0];
    const float* cosT  = (const float*)d_in[1];
    const float* sinT  = (const float*)d_in[2];
    const float* w_qkv = (const float*)d_in[3];
    const float* w_out = (const float*)d_in[4];
    float* out = (float*)d_out;

    cudaFuncSetAttribute(mma_gemm<0>,
                         cudaFuncAttributeMaxDynamicSharedMemorySize, GSMEM);
    cudaFuncSetAttribute(mma_gemm<1>,
                         cudaFuncAttributeMaxDynamicSharedMemorySize, GSMEM);
    cudaFuncSetAttribute(attn_mma,
                         cudaFuncAttributeMaxDynamicSharedMemorySize, ATTN_SMEM2);

    // 0. Split inputs to bf16 hi/lo
    split_kernel<0><<<(Mz * Dz) / 1024, 256>>>(x);
    split_kernel<1><<<(3 * Dz * Dz) / 1024, 256>>>(w_qkv);
    split_kernel<2><<<(Dz * Dz) / 1024, 256>>>(w_out);

    // 1. QKV projection (bf16x3) -> q,k fp32 [bh][t][d]; v bf16 hi/lo
    mma_gemm<0><<<dim3(48, 64), 256, GSMEM>>>(nullptr);

    // 2. RoPE + scale + split q,k to bf16 hi/lo
    rope_kernel<<<(BHz * Tz * 64) / 256, 256>>>(cosT, sinT);

    // 3. Causal flash attention (bf16x3 tensor cores) -> o bf16 hi/lo
    attn_mma<<<dim3(Tz / 128, BHz), 256, ATTN_SMEM2>>>();

    // 4. Output projection (bf16x3)
    mma_gemm<1><<<dim3(16, 64), 256, GSMEM>>>(out);
}